// round 13
// baseline (speedup 1.0000x reference)
#include <cuda_runtime.h>
#include <cuda_bf16.h>
#include <cuda_fp16.h>
#include <math.h>

#define N_NODES 100000
#define N_EDGES 1600000
#define IN_F 128
#define HID 128
#define NC 10
#define NCP 12
#define SCAN_B 98
#define SCAN_T 1024
#define MM1_TILES ((N_NODES + 255) / 256)   // 391
#define A_TILE 65536                         // 256x128 bf16
#define B_TILE 32768                         // 128x128 bf16
#define MM1_SMEM (2 * A_TILE + 2 * B_TILE)   // 192KB

// ---------------- scratch (static device globals; no allocs) ----------------
__device__ int   g_is64;
__device__ int   g_deg   [N_NODES];
__device__ int   g_rowptr[N_NODES];
__device__ int   g_cursor[N_NODES];
__device__ float g_dinv  [N_NODES];
__device__ int   g_col   [N_EDGES];
__device__ int   g_src   [N_EDGES];
__device__ int   g_dst   [N_EDGES];
__device__ int   g_bsum  [SCAN_B];
__device__ int   g_boff  [SCAN_B];
__device__ unsigned short gWhi[HID * IN_F];   // W1^T split hi, [n][k] bf16
__device__ unsigned short gWlo[HID * IN_F];   // W1^T split lo
__device__ __align__(16) __half g_h1[N_NODES * HID];   // X @ W1, fp16
__device__ __align__(16) float  g_h2[N_NODES * NCP];

// swizzled byte offset in a Rx128 bf16 tile (row r, k col; k multiple of 4)
__device__ __forceinline__ unsigned tile_off(int r, int k) {
    return (unsigned)(r * 256 + ((((k >> 3) ^ (r & 7)) << 4)) + (k & 7) * 2);
}
__device__ __forceinline__ unsigned smem_u32(const void* p) {
    unsigned a;
    asm("{ .reg .u64 t; cvta.to.shared.u64 t, %1; cvt.u32.u64 %0, t; }" : "=r"(a) : "l"(p));
    return a;
}
#define LDSM4(r0, r1, r2, r3, addr) \
    asm volatile("ldmatrix.sync.aligned.m8n8.x4.shared.b16 {%0,%1,%2,%3}, [%4];" \
                 : "=r"(r0), "=r"(r1), "=r"(r2), "=r"(r3) : "r"(addr))
#define MMA16816(d0, d1, d2, d3, a0, a1, a2, a3, b0, b1) \
    asm volatile("mma.sync.aligned.m16n8k16.row.col.f32.bf16.bf16.f32 " \
                 "{%0,%1,%2,%3}, {%4,%5,%6,%7}, {%8,%9}, {%0,%1,%2,%3};" \
                 : "+f"(d0), "+f"(d1), "+f"(d2), "+f"(d3) \
                 : "r"(a0), "r"(a1), "r"(a2), "r"(a3), "r"(b0), "r"(b1))

__device__ __forceinline__ void fma_h4(float4& acc, uint2 u, float nrm) {
    float2 p0 = __half22float2(*(__half2*)&u.x);
    float2 p1 = __half22float2(*(__half2*)&u.y);
    acc.x = fmaf(p0.x, nrm, acc.x);
    acc.y = fmaf(p0.y, nrm, acc.y);
    acc.z = fmaf(p1.x, nrm, acc.z);
    acc.w = fmaf(p1.y, nrm, acc.w);
}

// ---------------- dtype sniff ----------------
__global__ void detect_dtype(const int* __restrict__ raw) {
    if (threadIdx.x == 0 && blockIdx.x == 0) {
        int any = 0;
        #pragma unroll
        for (int k = 0; k < 8; k++) any |= raw[2 * k + 1];
        g_is64 = (any == 0) ? 1 : 0;
    }
}

__global__ void zero_deg() {
    int i = blockIdx.x * blockDim.x + threadIdx.x;
    if (i < N_NODES) g_deg[i] = 0;
}

__global__ void convert_edges(const int* __restrict__ raw) {
    int e = blockIdx.x * blockDim.x + threadIdx.x;
    if (e >= N_EDGES) return;
    int s, d;
    if (g_is64) {
        s = ((const int2*)raw)[e].x;
        d = ((const int2*)raw)[N_EDGES + e].x;
    } else {
        s = raw[e];
        d = raw[N_EDGES + e];
    }
    g_src[e] = s;
    g_dst[e] = d;
    atomicAdd(&g_deg[d], 1);
}

// ---------------- W1 split ----------------
__global__ void w_split(const float* __restrict__ W1) {
    int idx = blockIdx.x * blockDim.x + threadIdx.x;
    if (idx >= HID * IN_F) return;
    int n = idx >> 7, k = idx & 127;
    float w = W1[k * HID + n];
    __nv_bfloat16 hi = __float2bfloat16(w);
    __nv_bfloat16 lo = __float2bfloat16(w - __bfloat162float(hi));
    gWhi[idx] = __bfloat16_as_ushort(hi);
    gWlo[idx] = __bfloat16_as_ushort(lo);
}

// ---------------- scans ----------------
__global__ void __launch_bounds__(SCAN_T) scanA() {
    __shared__ int wsum[32];
    int i = blockIdx.x * SCAN_T + threadIdx.x;
    int lane = threadIdx.x & 31, warp = threadIdx.x >> 5;
    int d = (i < N_NODES) ? g_deg[i] : 0;
    int v = d;
    #pragma unroll
    for (int o = 16; o; o >>= 1) v += __shfl_xor_sync(0xFFFFFFFFu, v, o);
    if (lane == 0) wsum[warp] = v;
    __syncthreads();
    if (warp == 0) {
        int w = wsum[lane];
        #pragma unroll
        for (int o = 16; o; o >>= 1) w += __shfl_xor_sync(0xFFFFFFFFu, w, o);
        if (lane == 0) g_bsum[blockIdx.x] = w;
    }
}
__global__ void __launch_bounds__(128) scanB() {
    __shared__ int wsum[4];
    int t = threadIdx.x;
    int lane = t & 31, warp = t >> 5;
    int s = (t < SCAN_B) ? g_bsum[t] : 0;
    int v = s;
    #pragma unroll
    for (int o = 1; o < 32; o <<= 1) {
        int n = __shfl_up_sync(0xFFFFFFFFu, v, o);
        if (lane >= o) v += n;
    }
    if (lane == 31) wsum[warp] = v;
    __syncthreads();
    int off = 0;
    for (int w = 0; w < warp; w++) off += wsum[w];
    if (t < SCAN_B) g_boff[t] = off + v - s;
}
__global__ void __launch_bounds__(SCAN_T) scanC() {
    __shared__ int wsum[32];
    int i = blockIdx.x * SCAN_T + threadIdx.x;
    int lane = threadIdx.x & 31, warp = threadIdx.x >> 5;
    int d = (i < N_NODES) ? g_deg[i] : 0;
    int v = d;
    #pragma unroll
    for (int o = 1; o < 32; o <<= 1) {
        int n = __shfl_up_sync(0xFFFFFFFFu, v, o);
        if (lane >= o) v += n;
    }
    if (lane == 31) wsum[warp] = v;
    __syncthreads();
    if (warp == 0) {
        int w = wsum[lane];
        #pragma unroll
        for (int o = 1; o < 32; o <<= 1) {
            int n = __shfl_up_sync(0xFFFFFFFFu, w, o);
            if (lane >= o) w += n;
        }
        wsum[lane] = w;
    }
    __syncthreads();
    if (i < N_NODES) {
        int p = g_boff[blockIdx.x] + (warp ? wsum[warp - 1] : 0) + (v - d);
        g_rowptr[i] = p;
        g_cursor[i] = p;
        g_dinv[i]   = rsqrtf((float)d + 1.0f);
    }
}

__global__ void fill_csr() {
    int e = blockIdx.x * blockDim.x + threadIdx.x;
    if (e < N_EDGES) {
        int p = atomicAdd(&g_cursor[g_dst[e]], 1);
        g_col[p] = g_src[e];
    }
}

// ---------------- mm1: 512 threads, CTA tile 256x128; warp tile 32x64; fp16 output ----------------
__global__ void __launch_bounds__(512) mm1_mma(const float* __restrict__ x) {
    extern __shared__ char sm[];
    char* smAhi = sm;
    char* smAlo = sm + A_TILE;
    char* smBhi = sm + 2 * A_TILE;
    char* smBlo = sm + 2 * A_TILE + B_TILE;

    const int tid = threadIdx.x;
    const int wid = tid >> 5, lane = tid & 31;
    const int row0 = blockIdx.x * 256;

    #pragma unroll 4
    for (int it = 0; it < 16; it++) {
        int idx4 = tid + it * 512;
        int r  = idx4 >> 5;
        int k0 = (idx4 & 31) * 4;
        int grow = row0 + r;
        float4 v = make_float4(0.f, 0.f, 0.f, 0.f);
        if (grow < N_NODES) v = ((const float4*)x)[(size_t)grow * 32 + (idx4 & 31)];
        __nv_bfloat16 h0 = __float2bfloat16(v.x), h1b = __float2bfloat16(v.y);
        __nv_bfloat16 h2 = __float2bfloat16(v.z), h3 = __float2bfloat16(v.w);
        __nv_bfloat16 l0 = __float2bfloat16(v.x - __bfloat162float(h0));
        __nv_bfloat16 l1 = __float2bfloat16(v.y - __bfloat162float(h1b));
        __nv_bfloat16 l2 = __float2bfloat16(v.z - __bfloat162float(h2));
        __nv_bfloat16 l3 = __float2bfloat16(v.w - __bfloat162float(h3));
        unsigned hiA = (unsigned)__bfloat16_as_ushort(h0) | ((unsigned)__bfloat16_as_ushort(h1b) << 16);
        unsigned hiB = (unsigned)__bfloat16_as_ushort(h2) | ((unsigned)__bfloat16_as_ushort(h3) << 16);
        unsigned loA = (unsigned)__bfloat16_as_ushort(l0) | ((unsigned)__bfloat16_as_ushort(l1) << 16);
        unsigned loB = (unsigned)__bfloat16_as_ushort(l2) | ((unsigned)__bfloat16_as_ushort(l3) << 16);
        unsigned off = tile_off(r, k0);
        *(uint2*)(smAhi + off) = make_uint2(hiA, hiB);
        *(uint2*)(smAlo + off) = make_uint2(loA, loB);
    }

    #pragma unroll 4
    for (int it = 0; it < 8; it++) {
        int idx4 = tid + it * 512;
        int n  = idx4 >> 5;
        int k0 = (idx4 & 31) * 4;
        uint2 bh = *(const uint2*)(gWhi + n * 128 + k0);
        uint2 bl = *(const uint2*)(gWlo + n * 128 + k0);
        unsigned off = tile_off(n, k0);
        *(uint2*)(smBhi + off) = bh;
        *(uint2*)(smBlo + off) = bl;
    }
    __syncthreads();

    const int wm = (wid & 7) * 32;
    const int wn = (wid >> 3) * 64;
    const int a_lrow = lane & 15;
    const int a_koff = (lane & 16) ? 8 : 0;
    const int b_lrow = (lane & 7) + ((lane & 16) ? 8 : 0);
    const int b_koff = (lane & 8) ? 8 : 0;

    float d[2][4][8];
    #pragma unroll
    for (int a = 0; a < 2; a++)
        #pragma unroll
        for (int b = 0; b < 4; b++)
            #pragma unroll
            for (int c = 0; c < 8; c++) d[a][b][c] = 0.f;

    #pragma unroll
    for (int ks = 0; ks < 8; ks++) {
        int k = ks * 16;
        unsigned a0h0, a0h1, a0h2, a0h3, a1h0, a1h1, a1h2, a1h3;
        unsigned a0l0, a0l1, a0l2, a0l3, a1l0, a1l1, a1l2, a1l3;
        unsigned aoff0 = tile_off(wm + a_lrow, k + a_koff);
        unsigned aoff1 = tile_off(wm + 16 + a_lrow, k + a_koff);
        LDSM4(a0h0, a0h1, a0h2, a0h3, smem_u32(smAhi + aoff0));
        LDSM4(a1h0, a1h1, a1h2, a1h3, smem_u32(smAhi + aoff1));
        LDSM4(a0l0, a0l1, a0l2, a0l3, smem_u32(smAlo + aoff0));
        LDSM4(a1l0, a1l1, a1l2, a1l3, smem_u32(smAlo + aoff1));
        #pragma unroll
        for (int nt = 0; nt < 4; nt++) {
            float* d0 = d[0][nt];
            float* d1 = d[1][nt];
            unsigned boff = tile_off(wn + nt * 16 + b_lrow, k + b_koff);
            unsigned b0, b1, b2, b3;
            LDSM4(b0, b1, b2, b3, smem_u32(smBhi + boff));
            MMA16816(d0[0], d0[1], d0[2], d0[3], a0h0, a0h1, a0h2, a0h3, b0, b1);
            MMA16816(d0[4], d0[5], d0[6], d0[7], a0h0, a0h1, a0h2, a0h3, b2, b3);
            MMA16816(d1[0], d1[1], d1[2], d1[3], a1h0, a1h1, a1h2, a1h3, b0, b1);
            MMA16816(d1[4], d1[5], d1[6], d1[7], a1h0, a1h1, a1h2, a1h3, b2, b3);
            MMA16816(d0[0], d0[1], d0[2], d0[3], a0l0, a0l1, a0l2, a0l3, b0, b1);
            MMA16816(d0[4], d0[5], d0[6], d0[7], a0l0, a0l1, a0l2, a0l3, b2, b3);
            MMA16816(d1[0], d1[1], d1[2], d1[3], a1l0, a1l1, a1l2, a1l3, b0, b1);
            MMA16816(d1[4], d1[5], d1[6], d1[7], a1l0, a1l1, a1l2, a1l3, b2, b3);
            LDSM4(b0, b1, b2, b3, smem_u32(smBlo + boff));
            MMA16816(d0[0], d0[1], d0[2], d0[3], a0h0, a0h1, a0h2, a0h3, b0, b1);
            MMA16816(d0[4], d0[5], d0[6], d0[7], a0h0, a0h1, a0h2, a0h3, b2, b3);
            MMA16816(d1[0], d1[1], d1[2], d1[3], a1h0, a1h1, a1h2, a1h3, b0, b1);
            MMA16816(d1[4], d1[5], d1[6], d1[7], a1h0, a1h1, a1h2, a1h3, b2, b3);
        }
    }

    int g = lane >> 2, tig = lane & 3;
    #pragma unroll
    for (int mh = 0; mh < 2; mh++) {
        int rlo = row0 + wm + mh * 16 + g;
        int rhi = rlo + 8;
        #pragma unroll
        for (int nt = 0; nt < 4; nt++) {
            const float* de = d[mh][nt];
            #pragma unroll
            for (int h8 = 0; h8 < 2; h8++) {
                int col = wn + nt * 16 + h8 * 8 + tig * 2;
                if (rlo < N_NODES)
                    *(__half2*)(g_h1 + (size_t)rlo * HID + col) =
                        __floats2half2_rn(de[h8 * 4 + 0], de[h8 * 4 + 1]);
                if (rhi < N_NODES)
                    *(__half2*)(g_h1 + (size_t)rhi * HID + col) =
                        __floats2half2_rn(de[h8 * 4 + 2], de[h8 * 4 + 3]);
            }
        }
    }
}

// ---------------- gather1 fused with mm2 (h1 fp16, 8-wide MLP) ----------------
__global__ void __launch_bounds__(256) gather1_mm2(const float* __restrict__ b1,
                                                   const float* __restrict__ W2) {
    __shared__ float4 w2t4[NC * 32];
    for (int t = threadIdx.x; t < NC * 32; t += 256) {
        int c = t >> 5, l = t & 31;
        w2t4[t] = make_float4(W2[(4 * l + 0) * NC + c], W2[(4 * l + 1) * NC + c],
                              W2[(4 * l + 2) * NC + c], W2[(4 * l + 3) * NC + c]);
    }
    __syncthreads();

    int warp = threadIdx.x >> 5, lane = threadIdx.x & 31;
    int i = blockIdx.x * 8 + warp;
    if (i >= N_NODES) return;

    float dd = g_dinv[i];
    int start = g_rowptr[i], cnt = g_deg[i];

    float4 acc = make_float4(0.f, 0.f, 0.f, 0.f);
    {
        uint2 u = ((const uint2*)(g_h1 + (size_t)i * HID))[lane];
        fma_h4(acc, u, dd * dd);
    }

    for (int base = 0; base < cnt; base += 32) {
        int j = base + lane;
        int cid = 0; float nv = 0.f;
        if (j < cnt) { cid = g_col[start + j]; nv = g_dinv[cid]; }
        int m = cnt - base; if (m > 32) m = 32;
        int k = 0;
        // 8-wide: 8 independent LDG.64 in flight per warp
        for (; k + 8 <= m; k += 8) {
            int   s0 = __shfl_sync(0xFFFFFFFFu, cid, k);
            int   s1 = __shfl_sync(0xFFFFFFFFu, cid, k + 1);
            int   s2 = __shfl_sync(0xFFFFFFFFu, cid, k + 2);
            int   s3 = __shfl_sync(0xFFFFFFFFu, cid, k + 3);
            int   s4 = __shfl_sync(0xFFFFFFFFu, cid, k + 4);
            int   s5 = __shfl_sync(0xFFFFFFFFu, cid, k + 5);
            int   s6 = __shfl_sync(0xFFFFFFFFu, cid, k + 6);
            int   s7 = __shfl_sync(0xFFFFFFFFu, cid, k + 7);
            float n0 = __shfl_sync(0xFFFFFFFFu, nv, k)     * dd;
            float n1 = __shfl_sync(0xFFFFFFFFu, nv, k + 1) * dd;
            float n2 = __shfl_sync(0xFFFFFFFFu, nv, k + 2) * dd;
            float n3 = __shfl_sync(0xFFFFFFFFu, nv, k + 3) * dd;
            float n4 = __shfl_sync(0xFFFFFFFFu, nv, k + 4) * dd;
            float n5 = __shfl_sync(0xFFFFFFFFu, nv, k + 5) * dd;
            float n6 = __shfl_sync(0xFFFFFFFFu, nv, k + 6) * dd;
            float n7 = __shfl_sync(0xFFFFFFFFu, nv, k + 7) * dd;
            uint2 u0 = ((const uint2*)(g_h1 + (size_t)s0 * HID))[lane];
            uint2 u1 = ((const uint2*)(g_h1 + (size_t)s1 * HID))[lane];
            uint2 u2 = ((const uint2*)(g_h1 + (size_t)s2 * HID))[lane];
            uint2 u3 = ((const uint2*)(g_h1 + (size_t)s3 * HID))[lane];
            uint2 u4 = ((const uint2*)(g_h1 + (size_t)s4 * HID))[lane];
            uint2 u5 = ((const uint2*)(g_h1 + (size_t)s5 * HID))[lane];
            uint2 u6 = ((const uint2*)(g_h1 + (size_t)s6 * HID))[lane];
            uint2 u7 = ((const uint2*)(g_h1 + (size_t)s7 * HID))[lane];
            fma_h4(acc, u0, n0);
            fma_h4(acc, u1, n1);
            fma_h4(acc, u2, n2);
            fma_h4(acc, u3, n3);
            fma_h4(acc, u4, n4);
            fma_h4(acc, u5, n5);
            fma_h4(acc, u6, n6);
            fma_h4(acc, u7, n7);
        }
        for (; k < m; k++) {
            int   s   = __shfl_sync(0xFFFFFFFFu, cid, k);
            float nrm = __shfl_sync(0xFFFFFFFFu, nv,  k) * dd;
            uint2 u = ((const uint2*)(g_h1 + (size_t)s * HID))[lane];
            fma_h4(acc, u, nrm);
        }
    }
    float4 b = ((const float4*)b1)[lane];
    acc.x = fmaxf(acc.x + b.x, 0.f);
    acc.y = fmaxf(acc.y + b.y, 0.f);
    acc.z = fmaxf(acc.z + b.z, 0.f);
    acc.w = fmaxf(acc.w + b.w, 0.f);

    float r[NC];
    #pragma unroll
    for (int c = 0; c < NC; c++) {
        float4 w = w2t4[c * 32 + lane];
        float p = acc.x * w.x + acc.y * w.y + acc.z * w.z + acc.w * w.w;
        #pragma unroll
        for (int o = 16; o; o >>= 1) p += __shfl_xor_sync(0xFFFFFFFFu, p, o);
        r[c] = p;
    }
    if (lane == 0) {
        float* o = g_h2 + (size_t)i * NCP;
        *(float4*)(o)     = make_float4(r[0], r[1], r[2], r[3]);
        *(float4*)(o + 4) = make_float4(r[4], r[5], r[6], r[7]);
        *(float2*)(o + 8) = make_float2(r[8], r[9]);
    }
}

// ---------------- gather2 + softmax (8-wide MLP) ----------------
__global__ void __launch_bounds__(256) gather2(const float* __restrict__ b2,
                                               float* __restrict__ out) {
    int warp = threadIdx.x >> 5, lane = threadIdx.x & 31;
    int i = blockIdx.x * 8 + warp;
    if (i >= N_NODES) return;

    float dd = g_dinv[i];
    int start = g_rowptr[i], cnt = g_deg[i];

    float acc = 0.f;
    if (lane < NC) acc = g_h2[(size_t)i * NCP + lane] * dd * dd;

    for (int base = 0; base < cnt; base += 32) {
        int j = base + lane;
        int cid = 0; float nv = 0.f;
        if (j < cnt) { cid = g_col[start + j]; nv = g_dinv[cid]; }
        int m = cnt - base; if (m > 32) m = 32;
        int k = 0;
        for (; k + 8 <= m; k += 8) {
            int   s0 = __shfl_sync(0xFFFFFFFFu, cid, k);
            int   s1 = __shfl_sync(0xFFFFFFFFu, cid, k + 1);
            int   s2 = __shfl_sync(0xFFFFFFFFu, cid, k + 2);
            int   s3 = __shfl_sync(0xFFFFFFFFu, cid, k + 3);
            int   s4 = __shfl_sync(0xFFFFFFFFu, cid, k + 4);
            int   s5 = __shfl_sync(0xFFFFFFFFu, cid, k + 5);
            int   s6 = __shfl_sync(0xFFFFFFFFu, cid, k + 6);
            int   s7 = __shfl_sync(0xFFFFFFFFu, cid, k + 7);
            float n0 = __shfl_sync(0xFFFFFFFFu, nv, k)     * dd;
            float n1 = __shfl_sync(0xFFFFFFFFu, nv, k + 1) * dd;
            float n2 = __shfl_sync(0xFFFFFFFFu, nv, k + 2) * dd;
            float n3 = __shfl_sync(0xFFFFFFFFu, nv, k + 3) * dd;
            float n4 = __shfl_sync(0xFFFFFFFFu, nv, k + 4) * dd;
            float n5 = __shfl_sync(0xFFFFFFFFu, nv, k + 5) * dd;
            float n6 = __shfl_sync(0xFFFFFFFFu, nv, k + 6) * dd;
            float n7 = __shfl_sync(0xFFFFFFFFu, nv, k + 7) * dd;
            float v0 = 0.f, v1 = 0.f, v2 = 0.f, v3 = 0.f;
            float v4 = 0.f, v5 = 0.f, v6 = 0.f, v7 = 0.f;
            if (lane < NC) {
                v0 = g_h2[(size_t)s0 * NCP + lane];
                v1 = g_h2[(size_t)s1 * NCP + lane];
                v2 = g_h2[(size_t)s2 * NCP + lane];
                v3 = g_h2[(size_t)s3 * NCP + lane];
                v4 = g_h2[(size_t)s4 * NCP + lane];
                v5 = g_h2[(size_t)s5 * NCP + lane];
                v6 = g_h2[(size_t)s6 * NCP + lane];
                v7 = g_h2[(size_t)s7 * NCP + lane];
            }
            acc = fmaf(v0, n0, acc);
            acc = fmaf(v1, n1, acc);
            acc = fmaf(v2, n2, acc);
            acc = fmaf(v3, n3, acc);
            acc = fmaf(v4, n4, acc);
            acc = fmaf(v5, n5, acc);
            acc = fmaf(v6, n6, acc);
            acc = fmaf(v7, n7, acc);
        }
        for (; k < m; k++) {
            int   s   = __shfl_sync(0xFFFFFFFFu, cid, k);
            float nrm = __shfl_sync(0xFFFFFFFFu, nv,  k) * dd;
            float v = (lane < NC) ? g_h2[(size_t)s * NCP + lane] : 0.f;
            acc = fmaf(v, nrm, acc);
        }
    }

    float val = (lane < NC) ? acc + b2[lane] : -INFINITY;
    float mx = val;
    #pragma unroll
    for (int o = 16; o; o >>= 1) mx = fmaxf(mx, __shfl_xor_sync(0xFFFFFFFFu, mx, o));
    float e = (lane < NC) ? expf(val - mx) : 0.f;
    float ssum = e;
    #pragma unroll
    for (int o = 16; o; o >>= 1) ssum += __shfl_xor_sync(0xFFFFFFFFu, ssum, o);
    if (lane < NC) out[(size_t)i * NC + lane] = e / ssum;
}

// ---------------- launch ----------------
extern "C" void kernel_launch(void* const* d_in, const int* in_sizes, int n_in,
                              void* d_out, int out_size) {
    const float* x  = (const float*)d_in[0];
    const int*   ei = (const int*)d_in[1];
    const float* W1 = (const float*)d_in[2];
    const float* b1 = (const float*)d_in[3];
    const float* W2 = (const float*)d_in[4];
    const float* b2 = (const float*)d_in[5];
    float* out = (float*)d_out;

    static bool attrDone = false;
    if (!attrDone) {
        cudaFuncSetAttribute(mm1_mma, cudaFuncAttributeMaxDynamicSharedMemorySize, MM1_SMEM);
        attrDone = true;
    }

    w_split<<<(HID * IN_F + 255) / 256, 256>>>(W1);      // 0
    detect_dtype<<<1, 32>>>(ei);                          // 1
    zero_deg<<<(N_NODES + 255) / 256, 256>>>();           // 2
    mm1_mma<<<MM1_TILES, 512, MM1_SMEM>>>(x);             // 3  <- profiled slot
    convert_edges<<<(N_EDGES + 255) / 256, 256>>>(ei);    // 4
    scanA<<<SCAN_B, SCAN_T>>>();
    scanB<<<1, 128>>>();
    scanC<<<SCAN_B, SCAN_T>>>();
    fill_csr<<<(N_EDGES + 255) / 256, 256>>>();

    gather1_mm2<<<N_NODES / 8, 256>>>(b1, W2);
    gather2<<<N_NODES / 8, 256>>>(b2, out);
}

// round 14
// speedup vs baseline: 1.4777x; 1.4777x over previous
#include <cuda_runtime.h>
#include <cuda_bf16.h>
#include <cuda_fp16.h>
#include <math.h>

#define N_NODES 100000
#define N_EDGES 1600000
#define IN_F 128
#define HID 128
#define NC 10
#define NCP 12
#define SCAN_B 98
#define SCAN_T 1024
#define MM1_TILES ((N_NODES + 255) / 256)   // 391
#define A_TILE 65536                         // 256x128 bf16
#define B_TILE 32768                         // 128x128 bf16
#define MM1_SMEM (2 * A_TILE + 2 * B_TILE)   // 192KB

// ---------------- scratch (static device globals; no allocs) ----------------
__device__ int   g_is64;
__device__ int   g_deg   [N_NODES];
__device__ int   g_rowptr[N_NODES];
__device__ int   g_cursor[N_NODES];
__device__ float g_dinv  [N_NODES];
__device__ int   g_col   [N_EDGES];
__device__ int   g_src   [N_EDGES];
__device__ int   g_dst   [N_EDGES];
__device__ int   g_bsum  [SCAN_B];
__device__ int   g_boff  [SCAN_B];
__device__ unsigned short gWhi[HID * IN_F];   // W1^T split hi, [n][k] bf16
__device__ unsigned short gWlo[HID * IN_F];   // W1^T split lo
__device__ __align__(16) __half g_h1[N_NODES * HID];   // X @ W1, fp16
__device__ __align__(16) float  g_h2[N_NODES * NCP];

// swizzled byte offset in a Rx128 bf16 tile (row r, k col; k multiple of 4)
__device__ __forceinline__ unsigned tile_off(int r, int k) {
    return (unsigned)(r * 256 + ((((k >> 3) ^ (r & 7)) << 4)) + (k & 7) * 2);
}
__device__ __forceinline__ unsigned smem_u32(const void* p) {
    unsigned a;
    asm("{ .reg .u64 t; cvta.to.shared.u64 t, %1; cvt.u32.u64 %0, t; }" : "=r"(a) : "l"(p));
    return a;
}
#define LDSM4(r0, r1, r2, r3, addr) \
    asm volatile("ldmatrix.sync.aligned.m8n8.x4.shared.b16 {%0,%1,%2,%3}, [%4];" \
                 : "=r"(r0), "=r"(r1), "=r"(r2), "=r"(r3) : "r"(addr))
#define MMA16816(d0, d1, d2, d3, a0, a1, a2, a3, b0, b1) \
    asm volatile("mma.sync.aligned.m16n8k16.row.col.f32.bf16.bf16.f32 " \
                 "{%0,%1,%2,%3}, {%4,%5,%6,%7}, {%8,%9}, {%0,%1,%2,%3};" \
                 : "+f"(d0), "+f"(d1), "+f"(d2), "+f"(d3) \
                 : "r"(a0), "r"(a1), "r"(a2), "r"(a3), "r"(b0), "r"(b1))

__device__ __forceinline__ void fma_h4(float4& acc, uint2 u, float nrm) {
    float2 p0 = __half22float2(*(__half2*)&u.x);
    float2 p1 = __half22float2(*(__half2*)&u.y);
    acc.x = fmaf(p0.x, nrm, acc.x);
    acc.y = fmaf(p0.y, nrm, acc.y);
    acc.z = fmaf(p1.x, nrm, acc.z);
    acc.w = fmaf(p1.y, nrm, acc.w);
}

// ---------------- dtype sniff ----------------
__global__ void detect_dtype(const int* __restrict__ raw) {
    if (threadIdx.x == 0 && blockIdx.x == 0) {
        int any = 0;
        #pragma unroll
        for (int k = 0; k < 8; k++) any |= raw[2 * k + 1];
        g_is64 = (any == 0) ? 1 : 0;
    }
}

__global__ void zero_deg() {
    int i = blockIdx.x * blockDim.x + threadIdx.x;
    if (i < N_NODES) g_deg[i] = 0;
}

__global__ void convert_edges(const int* __restrict__ raw) {
    int e = blockIdx.x * blockDim.x + threadIdx.x;
    if (e >= N_EDGES) return;
    int s, d;
    if (g_is64) {
        s = ((const int2*)raw)[e].x;
        d = ((const int2*)raw)[N_EDGES + e].x;
    } else {
        s = raw[e];
        d = raw[N_EDGES + e];
    }
    g_src[e] = s;
    g_dst[e] = d;
    atomicAdd(&g_deg[d], 1);
}

// ---------------- W1 split ----------------
__global__ void w_split(const float* __restrict__ W1) {
    int idx = blockIdx.x * blockDim.x + threadIdx.x;
    if (idx >= HID * IN_F) return;
    int n = idx >> 7, k = idx & 127;
    float w = W1[k * HID + n];
    __nv_bfloat16 hi = __float2bfloat16(w);
    __nv_bfloat16 lo = __float2bfloat16(w - __bfloat162float(hi));
    gWhi[idx] = __bfloat16_as_ushort(hi);
    gWlo[idx] = __bfloat16_as_ushort(lo);
}

// ---------------- scans ----------------
__global__ void __launch_bounds__(SCAN_T) scanA() {
    __shared__ int wsum[32];
    int i = blockIdx.x * SCAN_T + threadIdx.x;
    int lane = threadIdx.x & 31, warp = threadIdx.x >> 5;
    int d = (i < N_NODES) ? g_deg[i] : 0;
    int v = d;
    #pragma unroll
    for (int o = 16; o; o >>= 1) v += __shfl_xor_sync(0xFFFFFFFFu, v, o);
    if (lane == 0) wsum[warp] = v;
    __syncthreads();
    if (warp == 0) {
        int w = wsum[lane];
        #pragma unroll
        for (int o = 16; o; o >>= 1) w += __shfl_xor_sync(0xFFFFFFFFu, w, o);
        if (lane == 0) g_bsum[blockIdx.x] = w;
    }
}
__global__ void __launch_bounds__(128) scanB() {
    __shared__ int wsum[4];
    int t = threadIdx.x;
    int lane = t & 31, warp = t >> 5;
    int s = (t < SCAN_B) ? g_bsum[t] : 0;
    int v = s;
    #pragma unroll
    for (int o = 1; o < 32; o <<= 1) {
        int n = __shfl_up_sync(0xFFFFFFFFu, v, o);
        if (lane >= o) v += n;
    }
    if (lane == 31) wsum[warp] = v;
    __syncthreads();
    int off = 0;
    for (int w = 0; w < warp; w++) off += wsum[w];
    if (t < SCAN_B) g_boff[t] = off + v - s;
}
__global__ void __launch_bounds__(SCAN_T) scanC() {
    __shared__ int wsum[32];
    int i = blockIdx.x * SCAN_T + threadIdx.x;
    int lane = threadIdx.x & 31, warp = threadIdx.x >> 5;
    int d = (i < N_NODES) ? g_deg[i] : 0;
    int v = d;
    #pragma unroll
    for (int o = 1; o < 32; o <<= 1) {
        int n = __shfl_up_sync(0xFFFFFFFFu, v, o);
        if (lane >= o) v += n;
    }
    if (lane == 31) wsum[warp] = v;
    __syncthreads();
    if (warp == 0) {
        int w = wsum[lane];
        #pragma unroll
        for (int o = 1; o < 32; o <<= 1) {
            int n = __shfl_up_sync(0xFFFFFFFFu, w, o);
            if (lane >= o) w += n;
        }
        wsum[lane] = w;
    }
    __syncthreads();
    if (i < N_NODES) {
        int p = g_boff[blockIdx.x] + (warp ? wsum[warp - 1] : 0) + (v - d);
        g_rowptr[i] = p;
        g_cursor[i] = p;
        g_dinv[i]   = rsqrtf((float)d + 1.0f);
    }
}

__global__ void fill_csr() {
    int e = blockIdx.x * blockDim.x + threadIdx.x;
    if (e < N_EDGES) {
        int p = atomicAdd(&g_cursor[g_dst[e]], 1);
        g_col[p] = g_src[e];
    }
}

// ---------------- mm1: 512 threads, CTA tile 256x128; warp tile 32x64; fp16 output ----------------
__global__ void __launch_bounds__(512) mm1_mma(const float* __restrict__ x) {
    extern __shared__ char sm[];
    char* smAhi = sm;
    char* smAlo = sm + A_TILE;
    char* smBhi = sm + 2 * A_TILE;
    char* smBlo = sm + 2 * A_TILE + B_TILE;

    const int tid = threadIdx.x;
    const int wid = tid >> 5, lane = tid & 31;
    const int row0 = blockIdx.x * 256;

    #pragma unroll 4
    for (int it = 0; it < 16; it++) {
        int idx4 = tid + it * 512;
        int r  = idx4 >> 5;
        int k0 = (idx4 & 31) * 4;
        int grow = row0 + r;
        float4 v = make_float4(0.f, 0.f, 0.f, 0.f);
        if (grow < N_NODES) v = ((const float4*)x)[(size_t)grow * 32 + (idx4 & 31)];
        __nv_bfloat16 h0 = __float2bfloat16(v.x), h1b = __float2bfloat16(v.y);
        __nv_bfloat16 h2 = __float2bfloat16(v.z), h3 = __float2bfloat16(v.w);
        __nv_bfloat16 l0 = __float2bfloat16(v.x - __bfloat162float(h0));
        __nv_bfloat16 l1 = __float2bfloat16(v.y - __bfloat162float(h1b));
        __nv_bfloat16 l2 = __float2bfloat16(v.z - __bfloat162float(h2));
        __nv_bfloat16 l3 = __float2bfloat16(v.w - __bfloat162float(h3));
        unsigned hiA = (unsigned)__bfloat16_as_ushort(h0) | ((unsigned)__bfloat16_as_ushort(h1b) << 16);
        unsigned hiB = (unsigned)__bfloat16_as_ushort(h2) | ((unsigned)__bfloat16_as_ushort(h3) << 16);
        unsigned loA = (unsigned)__bfloat16_as_ushort(l0) | ((unsigned)__bfloat16_as_ushort(l1) << 16);
        unsigned loB = (unsigned)__bfloat16_as_ushort(l2) | ((unsigned)__bfloat16_as_ushort(l3) << 16);
        unsigned off = tile_off(r, k0);
        *(uint2*)(smAhi + off) = make_uint2(hiA, hiB);
        *(uint2*)(smAlo + off) = make_uint2(loA, loB);
    }

    #pragma unroll 4
    for (int it = 0; it < 8; it++) {
        int idx4 = tid + it * 512;
        int n  = idx4 >> 5;
        int k0 = (idx4 & 31) * 4;
        uint2 bh = *(const uint2*)(gWhi + n * 128 + k0);
        uint2 bl = *(const uint2*)(gWlo + n * 128 + k0);
        unsigned off = tile_off(n, k0);
        *(uint2*)(smBhi + off) = bh;
        *(uint2*)(smBlo + off) = bl;
    }
    __syncthreads();

    const int wm = (wid & 7) * 32;
    const int wn = (wid >> 3) * 64;
    const int a_lrow = lane & 15;
    const int a_koff = (lane & 16) ? 8 : 0;
    const int b_lrow = (lane & 7) + ((lane & 16) ? 8 : 0);
    const int b_koff = (lane & 8) ? 8 : 0;

    float d[2][4][8];
    #pragma unroll
    for (int a = 0; a < 2; a++)
        #pragma unroll
        for (int b = 0; b < 4; b++)
            #pragma unroll
            for (int c = 0; c < 8; c++) d[a][b][c] = 0.f;

    #pragma unroll
    for (int ks = 0; ks < 8; ks++) {
        int k = ks * 16;
        unsigned a0h0, a0h1, a0h2, a0h3, a1h0, a1h1, a1h2, a1h3;
        unsigned a0l0, a0l1, a0l2, a0l3, a1l0, a1l1, a1l2, a1l3;
        unsigned aoff0 = tile_off(wm + a_lrow, k + a_koff);
        unsigned aoff1 = tile_off(wm + 16 + a_lrow, k + a_koff);
        LDSM4(a0h0, a0h1, a0h2, a0h3, smem_u32(smAhi + aoff0));
        LDSM4(a1h0, a1h1, a1h2, a1h3, smem_u32(smAhi + aoff1));
        LDSM4(a0l0, a0l1, a0l2, a0l3, smem_u32(smAlo + aoff0));
        LDSM4(a1l0, a1l1, a1l2, a1l3, smem_u32(smAlo + aoff1));
        #pragma unroll
        for (int nt = 0; nt < 4; nt++) {
            float* d0 = d[0][nt];
            float* d1 = d[1][nt];
            unsigned boff = tile_off(wn + nt * 16 + b_lrow, k + b_koff);
            unsigned b0, b1, b2, b3;
            LDSM4(b0, b1, b2, b3, smem_u32(smBhi + boff));
            MMA16816(d0[0], d0[1], d0[2], d0[3], a0h0, a0h1, a0h2, a0h3, b0, b1);
            MMA16816(d0[4], d0[5], d0[6], d0[7], a0h0, a0h1, a0h2, a0h3, b2, b3);
            MMA16816(d1[0], d1[1], d1[2], d1[3], a1h0, a1h1, a1h2, a1h3, b0, b1);
            MMA16816(d1[4], d1[5], d1[6], d1[7], a1h0, a1h1, a1h2, a1h3, b2, b3);
            MMA16816(d0[0], d0[1], d0[2], d0[3], a0l0, a0l1, a0l2, a0l3, b0, b1);
            MMA16816(d0[4], d0[5], d0[6], d0[7], a0l0, a0l1, a0l2, a0l3, b2, b3);
            MMA16816(d1[0], d1[1], d1[2], d1[3], a1l0, a1l1, a1l2, a1l3, b0, b1);
            MMA16816(d1[4], d1[5], d1[6], d1[7], a1l0, a1l1, a1l2, a1l3, b2, b3);
            LDSM4(b0, b1, b2, b3, smem_u32(smBlo + boff));
            MMA16816(d0[0], d0[1], d0[2], d0[3], a0h0, a0h1, a0h2, a0h3, b0, b1);
            MMA16816(d0[4], d0[5], d0[6], d0[7], a0h0, a0h1, a0h2, a0h3, b2, b3);
            MMA16816(d1[0], d1[1], d1[2], d1[3], a1h0, a1h1, a1h2, a1h3, b0, b1);
            MMA16816(d1[4], d1[5], d1[6], d1[7], a1h0, a1h1, a1h2, a1h3, b2, b3);
        }
    }

    int g = lane >> 2, tig = lane & 3;
    #pragma unroll
    for (int mh = 0; mh < 2; mh++) {
        int rlo = row0 + wm + mh * 16 + g;
        int rhi = rlo + 8;
        #pragma unroll
        for (int nt = 0; nt < 4; nt++) {
            const float* de = d[mh][nt];
            #pragma unroll
            for (int h8 = 0; h8 < 2; h8++) {
                int col = wn + nt * 16 + h8 * 8 + tig * 2;
                if (rlo < N_NODES)
                    *(__half2*)(g_h1 + (size_t)rlo * HID + col) =
                        __floats2half2_rn(de[h8 * 4 + 0], de[h8 * 4 + 1]);
                if (rhi < N_NODES)
                    *(__half2*)(g_h1 + (size_t)rhi * HID + col) =
                        __floats2half2_rn(de[h8 * 4 + 2], de[h8 * 4 + 3]);
            }
        }
    }
}

// ---------------- gather1 fused with mm2 (h1 fp16, 4-wide MLP) ----------------
__global__ void __launch_bounds__(256) gather1_mm2(const float* __restrict__ b1,
                                                   const float* __restrict__ W2) {
    __shared__ float4 w2t4[NC * 32];
    for (int t = threadIdx.x; t < NC * 32; t += 256) {
        int c = t >> 5, l = t & 31;
        w2t4[t] = make_float4(W2[(4 * l + 0) * NC + c], W2[(4 * l + 1) * NC + c],
                              W2[(4 * l + 2) * NC + c], W2[(4 * l + 3) * NC + c]);
    }
    __syncthreads();

    int warp = threadIdx.x >> 5, lane = threadIdx.x & 31;
    int i = blockIdx.x * 8 + warp;
    if (i >= N_NODES) return;

    float dd = g_dinv[i];
    int start = g_rowptr[i], cnt = g_deg[i];

    float4 acc = make_float4(0.f, 0.f, 0.f, 0.f);
    {
        uint2 u = ((const uint2*)(g_h1 + (size_t)i * HID))[lane];
        fma_h4(acc, u, dd * dd);
    }

    for (int base = 0; base < cnt; base += 32) {
        int j = base + lane;
        int cid = 0; float nv = 0.f;
        if (j < cnt) { cid = g_col[start + j]; nv = g_dinv[cid]; }
        int m = cnt - base; if (m > 32) m = 32;
        int k = 0;
        for (; k + 4 <= m; k += 4) {
            int   s0 = __shfl_sync(0xFFFFFFFFu, cid, k);
            int   s1 = __shfl_sync(0xFFFFFFFFu, cid, k + 1);
            int   s2 = __shfl_sync(0xFFFFFFFFu, cid, k + 2);
            int   s3 = __shfl_sync(0xFFFFFFFFu, cid, k + 3);
            float n0 = __shfl_sync(0xFFFFFFFFu, nv, k)     * dd;
            float n1 = __shfl_sync(0xFFFFFFFFu, nv, k + 1) * dd;
            float n2 = __shfl_sync(0xFFFFFFFFu, nv, k + 2) * dd;
            float n3 = __shfl_sync(0xFFFFFFFFu, nv, k + 3) * dd;
            uint2 u0 = ((const uint2*)(g_h1 + (size_t)s0 * HID))[lane];
            uint2 u1 = ((const uint2*)(g_h1 + (size_t)s1 * HID))[lane];
            uint2 u2 = ((const uint2*)(g_h1 + (size_t)s2 * HID))[lane];
            uint2 u3 = ((const uint2*)(g_h1 + (size_t)s3 * HID))[lane];
            fma_h4(acc, u0, n0);
            fma_h4(acc, u1, n1);
            fma_h4(acc, u2, n2);
            fma_h4(acc, u3, n3);
        }
        for (; k < m; k++) {
            int   s   = __shfl_sync(0xFFFFFFFFu, cid, k);
            float nrm = __shfl_sync(0xFFFFFFFFu, nv,  k) * dd;
            uint2 u = ((const uint2*)(g_h1 + (size_t)s * HID))[lane];
            fma_h4(acc, u, nrm);
        }
    }
    float4 b = ((const float4*)b1)[lane];
    acc.x = fmaxf(acc.x + b.x, 0.f);
    acc.y = fmaxf(acc.y + b.y, 0.f);
    acc.z = fmaxf(acc.z + b.z, 0.f);
    acc.w = fmaxf(acc.w + b.w, 0.f);

    float r[NC];
    #pragma unroll
    for (int c = 0; c < NC; c++) {
        float4 w = w2t4[c * 32 + lane];
        float p = acc.x * w.x + acc.y * w.y + acc.z * w.z + acc.w * w.w;
        #pragma unroll
        for (int o = 16; o; o >>= 1) p += __shfl_xor_sync(0xFFFFFFFFu, p, o);
        r[c] = p;
    }
    if (lane == 0) {
        float* o = g_h2 + (size_t)i * NCP;
        *(float4*)(o)     = make_float4(r[0], r[1], r[2], r[3]);
        *(float4*)(o + 4) = make_float4(r[4], r[5], r[6], r[7]);
        *(float2*)(o + 8) = make_float2(r[8], r[9]);
    }
}

// ---------------- gather2 + softmax (4-wide MLP) ----------------
__global__ void __launch_bounds__(256) gather2(const float* __restrict__ b2,
                                               float* __restrict__ out) {
    int warp = threadIdx.x >> 5, lane = threadIdx.x & 31;
    int i = blockIdx.x * 8 + warp;
    if (i >= N_NODES) return;

    float dd = g_dinv[i];
    int start = g_rowptr[i], cnt = g_deg[i];

    float acc = 0.f;
    if (lane < NC) acc = g_h2[(size_t)i * NCP + lane] * dd * dd;

    for (int base = 0; base < cnt; base += 32) {
        int j = base + lane;
        int cid = 0; float nv = 0.f;
        if (j < cnt) { cid = g_col[start + j]; nv = g_dinv[cid]; }
        int m = cnt - base; if (m > 32) m = 32;
        int k = 0;
        for (; k + 4 <= m; k += 4) {
            int   s0 = __shfl_sync(0xFFFFFFFFu, cid, k);
            int   s1 = __shfl_sync(0xFFFFFFFFu, cid, k + 1);
            int   s2 = __shfl_sync(0xFFFFFFFFu, cid, k + 2);
            int   s3 = __shfl_sync(0xFFFFFFFFu, cid, k + 3);
            float n0 = __shfl_sync(0xFFFFFFFFu, nv, k)     * dd;
            float n1 = __shfl_sync(0xFFFFFFFFu, nv, k + 1) * dd;
            float n2 = __shfl_sync(0xFFFFFFFFu, nv, k + 2) * dd;
            float n3 = __shfl_sync(0xFFFFFFFFu, nv, k + 3) * dd;
            float v0 = 0.f, v1 = 0.f, v2 = 0.f, v3 = 0.f;
            if (lane < NC) {
                v0 = g_h2[(size_t)s0 * NCP + lane];
                v1 = g_h2[(size_t)s1 * NCP + lane];
                v2 = g_h2[(size_t)s2 * NCP + lane];
                v3 = g_h2[(size_t)s3 * NCP + lane];
            }
            acc = fmaf(v0, n0, acc);
            acc = fmaf(v1, n1, acc);
            acc = fmaf(v2, n2, acc);
            acc = fmaf(v3, n3, acc);
        }
        for (; k < m; k++) {
            int   s   = __shfl_sync(0xFFFFFFFFu, cid, k);
            float nrm = __shfl_sync(0xFFFFFFFFu, nv,  k) * dd;
            float v = (lane < NC) ? g_h2[(size_t)s * NCP + lane] : 0.f;
            acc = fmaf(v, nrm, acc);
        }
    }

    float val = (lane < NC) ? acc + b2[lane] : -INFINITY;
    float mx = val;
    #pragma unroll
    for (int o = 16; o; o >>= 1) mx = fmaxf(mx, __shfl_xor_sync(0xFFFFFFFFu, mx, o));
    float e = (lane < NC) ? expf(val - mx) : 0.f;
    float ssum = e;
    #pragma unroll
    for (int o = 16; o; o >>= 1) ssum += __shfl_xor_sync(0xFFFFFFFFu, ssum, o);
    if (lane < NC) out[(size_t)i * NC + lane] = e / ssum;
}

// ---------------- launch ----------------
extern "C" void kernel_launch(void* const* d_in, const int* in_sizes, int n_in,
                              void* d_out, int out_size) {
    const float* x  = (const float*)d_in[0];
    const int*   ei = (const int*)d_in[1];
    const float* W1 = (const float*)d_in[2];
    const float* b1 = (const float*)d_in[3];
    const float* W2 = (const float*)d_in[4];
    const float* b2 = (const float*)d_in[5];
    float* out = (float*)d_out;

    static bool attrDone = false;
    if (!attrDone) {
        cudaFuncSetAttribute(mm1_mma, cudaFuncAttributeMaxDynamicSharedMemorySize, MM1_SMEM);
        attrDone = true;
    }

    w_split<<<(HID * IN_F + 255) / 256, 256>>>(W1);      // 0
    detect_dtype<<<1, 32>>>(ei);                          // 1
    zero_deg<<<(N_NODES + 255) / 256, 256>>>();           // 2
    mm1_mma<<<MM1_TILES, 512, MM1_SMEM>>>(x);             // 3  <- profiled slot
    convert_edges<<<(N_EDGES + 255) / 256, 256>>>(ei);    // 4
    scanA<<<SCAN_B, SCAN_T>>>();
    scanB<<<1, 128>>>();
    scanC<<<SCAN_B, SCAN_T>>>();
    fill_csr<<<(N_EDGES + 255) / 256, 256>>>();

    gather1_mm2<<<N_NODES / 8, 256>>>(b1, W2);
    gather2<<<N_NODES / 8, 256>>>(b2, out);
}

// round 15
// speedup vs baseline: 1.5604x; 1.0560x over previous
#include <cuda_runtime.h>
#include <cuda_bf16.h>
#include <cuda_fp16.h>
#include <math.h>

#define N_NODES 100000
#define N_EDGES 1600000
#define IN_F 128
#define HID 128
#define NC 10
#define NCP 12
#define SCAN_B 98
#define SCAN_T 1024
#define MM1_TILES ((N_NODES + 255) / 256)   // 391
#define A_TILE 65536                         // 256x128 bf16
#define B_TILE 32768                         // 128x128 bf16
#define MM1_SMEM (2 * A_TILE + 2 * B_TILE)   // 192KB

// ---------------- scratch (static device globals; no allocs) ----------------
__device__ int   g_is64;
__device__ int   g_deg   [N_NODES];
__device__ int   g_rowptr[N_NODES];
__device__ int   g_cursor[N_NODES];
__device__ float g_dinv  [N_NODES];
__device__ __align__(16) int2 g_cole[N_EDGES];   // {src, bits(dinv[src])} per edge
__device__ int   g_src   [N_EDGES];
__device__ int   g_dst   [N_EDGES];
__device__ int   g_bsum  [SCAN_B];
__device__ int   g_boff  [SCAN_B];
__device__ unsigned short gWhi[HID * IN_F];   // W1^T split hi, [n][k] bf16
__device__ unsigned short gWlo[HID * IN_F];   // W1^T split lo
__device__ __align__(16) __half g_h1[N_NODES * HID];   // X @ W1, fp16
__device__ __align__(16) float  g_h2[N_NODES * NCP];

// swizzled byte offset in a Rx128 bf16 tile (row r, k col; k multiple of 4)
__device__ __forceinline__ unsigned tile_off(int r, int k) {
    return (unsigned)(r * 256 + ((((k >> 3) ^ (r & 7)) << 4)) + (k & 7) * 2);
}
__device__ __forceinline__ unsigned smem_u32(const void* p) {
    unsigned a;
    asm("{ .reg .u64 t; cvta.to.shared.u64 t, %1; cvt.u32.u64 %0, t; }" : "=r"(a) : "l"(p));
    return a;
}
#define LDSM4(r0, r1, r2, r3, addr) \
    asm volatile("ldmatrix.sync.aligned.m8n8.x4.shared.b16 {%0,%1,%2,%3}, [%4];" \
                 : "=r"(r0), "=r"(r1), "=r"(r2), "=r"(r3) : "r"(addr))
#define MMA16816(d0, d1, d2, d3, a0, a1, a2, a3, b0, b1) \
    asm volatile("mma.sync.aligned.m16n8k16.row.col.f32.bf16.bf16.f32 " \
                 "{%0,%1,%2,%3}, {%4,%5,%6,%7}, {%8,%9}, {%0,%1,%2,%3};" \
                 : "+f"(d0), "+f"(d1), "+f"(d2), "+f"(d3) \
                 : "r"(a0), "r"(a1), "r"(a2), "r"(a3), "r"(b0), "r"(b1))

__device__ __forceinline__ void fma_h4(float4& acc, uint2 u, float nrm) {
    float2 p0 = __half22float2(*(__half2*)&u.x);
    float2 p1 = __half22float2(*(__half2*)&u.y);
    acc.x = fmaf(p0.x, nrm, acc.x);
    acc.y = fmaf(p0.y, nrm, acc.y);
    acc.z = fmaf(p1.x, nrm, acc.z);
    acc.w = fmaf(p1.y, nrm, acc.w);
}

// ---------------- dtype sniff ----------------
__global__ void detect_dtype(const int* __restrict__ raw) {
    if (threadIdx.x == 0 && blockIdx.x == 0) {
        int any = 0;
        #pragma unroll
        for (int k = 0; k < 8; k++) any |= raw[2 * k + 1];
        g_is64 = (any == 0) ? 1 : 0;
    }
}

__global__ void zero_deg() {
    int i = blockIdx.x * blockDim.x + threadIdx.x;
    if (i < N_NODES) g_deg[i] = 0;
}

__global__ void convert_edges(const int* __restrict__ raw) {
    int e = blockIdx.x * blockDim.x + threadIdx.x;
    if (e >= N_EDGES) return;
    int s, d;
    if (g_is64) {
        s = ((const int2*)raw)[e].x;
        d = ((const int2*)raw)[N_EDGES + e].x;
    } else {
        s = raw[e];
        d = raw[N_EDGES + e];
    }
    g_src[e] = s;
    g_dst[e] = d;
    atomicAdd(&g_deg[d], 1);
}

// ---------------- W1 split ----------------
__global__ void w_split(const float* __restrict__ W1) {
    int idx = blockIdx.x * blockDim.x + threadIdx.x;
    if (idx >= HID * IN_F) return;
    int n = idx >> 7, k = idx & 127;
    float w = W1[k * HID + n];
    __nv_bfloat16 hi = __float2bfloat16(w);
    __nv_bfloat16 lo = __float2bfloat16(w - __bfloat162float(hi));
    gWhi[idx] = __bfloat16_as_ushort(hi);
    gWlo[idx] = __bfloat16_as_ushort(lo);
}

// ---------------- scans ----------------
__global__ void __launch_bounds__(SCAN_T) scanA() {
    __shared__ int wsum[32];
    int i = blockIdx.x * SCAN_T + threadIdx.x;
    int lane = threadIdx.x & 31, warp = threadIdx.x >> 5;
    int d = (i < N_NODES) ? g_deg[i] : 0;
    int v = d;
    #pragma unroll
    for (int o = 16; o; o >>= 1) v += __shfl_xor_sync(0xFFFFFFFFu, v, o);
    if (lane == 0) wsum[warp] = v;
    __syncthreads();
    if (warp == 0) {
        int w = wsum[lane];
        #pragma unroll
        for (int o = 16; o; o >>= 1) w += __shfl_xor_sync(0xFFFFFFFFu, w, o);
        if (lane == 0) g_bsum[blockIdx.x] = w;
    }
}
__global__ void __launch_bounds__(128) scanB() {
    __shared__ int wsum[4];
    int t = threadIdx.x;
    int lane = t & 31, warp = t >> 5;
    int s = (t < SCAN_B) ? g_bsum[t] : 0;
    int v = s;
    #pragma unroll
    for (int o = 1; o < 32; o <<= 1) {
        int n = __shfl_up_sync(0xFFFFFFFFu, v, o);
        if (lane >= o) v += n;
    }
    if (lane == 31) wsum[warp] = v;
    __syncthreads();
    int off = 0;
    for (int w = 0; w < warp; w++) off += wsum[w];
    if (t < SCAN_B) g_boff[t] = off + v - s;
}
__global__ void __launch_bounds__(SCAN_T) scanC() {
    __shared__ int wsum[32];
    int i = blockIdx.x * SCAN_T + threadIdx.x;
    int lane = threadIdx.x & 31, warp = threadIdx.x >> 5;
    int d = (i < N_NODES) ? g_deg[i] : 0;
    int v = d;
    #pragma unroll
    for (int o = 1; o < 32; o <<= 1) {
        int n = __shfl_up_sync(0xFFFFFFFFu, v, o);
        if (lane >= o) v += n;
    }
    if (lane == 31) wsum[warp] = v;
    __syncthreads();
    if (warp == 0) {
        int w = wsum[lane];
        #pragma unroll
        for (int o = 1; o < 32; o <<= 1) {
            int n = __shfl_up_sync(0xFFFFFFFFu, w, o);
            if (lane >= o) w += n;
        }
        wsum[lane] = w;
    }
    __syncthreads();
    if (i < N_NODES) {
        int p = g_boff[blockIdx.x] + (warp ? wsum[warp - 1] : 0) + (v - d);
        g_rowptr[i] = p;
        g_cursor[i] = p;
        g_dinv[i]   = rsqrtf((float)d + 1.0f);
    }
}

// ---------------- CSR fill: store {src, dinv[src]} per slot ----------------
__global__ void fill_csr() {
    int e = blockIdx.x * blockDim.x + threadIdx.x;
    if (e < N_EDGES) {
        int s = g_src[e];
        int d = g_dst[e];
        int p = atomicAdd(&g_cursor[d], 1);
        g_cole[p] = make_int2(s, __float_as_int(g_dinv[s]));
    }
}

// ---------------- mm1: 512 threads, CTA tile 256x128; warp tile 32x64; fp16 output ----------------
__global__ void __launch_bounds__(512) mm1_mma(const float* __restrict__ x) {
    extern __shared__ char sm[];
    char* smAhi = sm;
    char* smAlo = sm + A_TILE;
    char* smBhi = sm + 2 * A_TILE;
    char* smBlo = sm + 2 * A_TILE + B_TILE;

    const int tid = threadIdx.x;
    const int wid = tid >> 5, lane = tid & 31;
    const int row0 = blockIdx.x * 256;

    #pragma unroll 4
    for (int it = 0; it < 16; it++) {
        int idx4 = tid + it * 512;
        int r  = idx4 >> 5;
        int k0 = (idx4 & 31) * 4;
        int grow = row0 + r;
        float4 v = make_float4(0.f, 0.f, 0.f, 0.f);
        if (grow < N_NODES) v = ((const float4*)x)[(size_t)grow * 32 + (idx4 & 31)];
        __nv_bfloat16 h0 = __float2bfloat16(v.x), h1b = __float2bfloat16(v.y);
        __nv_bfloat16 h2 = __float2bfloat16(v.z), h3 = __float2bfloat16(v.w);
        __nv_bfloat16 l0 = __float2bfloat16(v.x - __bfloat162float(h0));
        __nv_bfloat16 l1 = __float2bfloat16(v.y - __bfloat162float(h1b));
        __nv_bfloat16 l2 = __float2bfloat16(v.z - __bfloat162float(h2));
        __nv_bfloat16 l3 = __float2bfloat16(v.w - __bfloat162float(h3));
        unsigned hiA = (unsigned)__bfloat16_as_ushort(h0) | ((unsigned)__bfloat16_as_ushort(h1b) << 16);
        unsigned hiB = (unsigned)__bfloat16_as_ushort(h2) | ((unsigned)__bfloat16_as_ushort(h3) << 16);
        unsigned loA = (unsigned)__bfloat16_as_ushort(l0) | ((unsigned)__bfloat16_as_ushort(l1) << 16);
        unsigned loB = (unsigned)__bfloat16_as_ushort(l2) | ((unsigned)__bfloat16_as_ushort(l3) << 16);
        unsigned off = tile_off(r, k0);
        *(uint2*)(smAhi + off) = make_uint2(hiA, hiB);
        *(uint2*)(smAlo + off) = make_uint2(loA, loB);
    }

    #pragma unroll 4
    for (int it = 0; it < 8; it++) {
        int idx4 = tid + it * 512;
        int n  = idx4 >> 5;
        int k0 = (idx4 & 31) * 4;
        uint2 bh = *(const uint2*)(gWhi + n * 128 + k0);
        uint2 bl = *(const uint2*)(gWlo + n * 128 + k0);
        unsigned off = tile_off(n, k0);
        *(uint2*)(smBhi + off) = bh;
        *(uint2*)(smBlo + off) = bl;
    }
    __syncthreads();

    const int wm = (wid & 7) * 32;
    const int wn = (wid >> 3) * 64;
    const int a_lrow = lane & 15;
    const int a_koff = (lane & 16) ? 8 : 0;
    const int b_lrow = (lane & 7) + ((lane & 16) ? 8 : 0);
    const int b_koff = (lane & 8) ? 8 : 0;

    float d[2][4][8];
    #pragma unroll
    for (int a = 0; a < 2; a++)
        #pragma unroll
        for (int b = 0; b < 4; b++)
            #pragma unroll
            for (int c = 0; c < 8; c++) d[a][b][c] = 0.f;

    #pragma unroll
    for (int ks = 0; ks < 8; ks++) {
        int k = ks * 16;
        unsigned a0h0, a0h1, a0h2, a0h3, a1h0, a1h1, a1h2, a1h3;
        unsigned a0l0, a0l1, a0l2, a0l3, a1l0, a1l1, a1l2, a1l3;
        unsigned aoff0 = tile_off(wm + a_lrow, k + a_koff);
        unsigned aoff1 = tile_off(wm + 16 + a_lrow, k + a_koff);
        LDSM4(a0h0, a0h1, a0h2, a0h3, smem_u32(smAhi + aoff0));
        LDSM4(a1h0, a1h1, a1h2, a1h3, smem_u32(smAhi + aoff1));
        LDSM4(a0l0, a0l1, a0l2, a0l3, smem_u32(smAlo + aoff0));
        LDSM4(a1l0, a1l1, a1l2, a1l3, smem_u32(smAlo + aoff1));
        #pragma unroll
        for (int nt = 0; nt < 4; nt++) {
            float* d0 = d[0][nt];
            float* d1 = d[1][nt];
            unsigned boff = tile_off(wn + nt * 16 + b_lrow, k + b_koff);
            unsigned b0, b1, b2, b3;
            LDSM4(b0, b1, b2, b3, smem_u32(smBhi + boff));
            MMA16816(d0[0], d0[1], d0[2], d0[3], a0h0, a0h1, a0h2, a0h3, b0, b1);
            MMA16816(d0[4], d0[5], d0[6], d0[7], a0h0, a0h1, a0h2, a0h3, b2, b3);
            MMA16816(d1[0], d1[1], d1[2], d1[3], a1h0, a1h1, a1h2, a1h3, b0, b1);
            MMA16816(d1[4], d1[5], d1[6], d1[7], a1h0, a1h1, a1h2, a1h3, b2, b3);
            MMA16816(d0[0], d0[1], d0[2], d0[3], a0l0, a0l1, a0l2, a0l3, b0, b1);
            MMA16816(d0[4], d0[5], d0[6], d0[7], a0l0, a0l1, a0l2, a0l3, b2, b3);
            MMA16816(d1[0], d1[1], d1[2], d1[3], a1l0, a1l1, a1l2, a1l3, b0, b1);
            MMA16816(d1[4], d1[5], d1[6], d1[7], a1l0, a1l1, a1l2, a1l3, b2, b3);
            LDSM4(b0, b1, b2, b3, smem_u32(smBlo + boff));
            MMA16816(d0[0], d0[1], d0[2], d0[3], a0h0, a0h1, a0h2, a0h3, b0, b1);
            MMA16816(d0[4], d0[5], d0[6], d0[7], a0h0, a0h1, a0h2, a0h3, b2, b3);
            MMA16816(d1[0], d1[1], d1[2], d1[3], a1h0, a1h1, a1h2, a1h3, b0, b1);
            MMA16816(d1[4], d1[5], d1[6], d1[7], a1h0, a1h1, a1h2, a1h3, b2, b3);
        }
    }

    int g = lane >> 2, tig = lane & 3;
    #pragma unroll
    for (int mh = 0; mh < 2; mh++) {
        int rlo = row0 + wm + mh * 16 + g;
        int rhi = rlo + 8;
        #pragma unroll
        for (int nt = 0; nt < 4; nt++) {
            const float* de = d[mh][nt];
            #pragma unroll
            for (int h8 = 0; h8 < 2; h8++) {
                int col = wn + nt * 16 + h8 * 8 + tig * 2;
                if (rlo < N_NODES)
                    *(__half2*)(g_h1 + (size_t)rlo * HID + col) =
                        __floats2half2_rn(de[h8 * 4 + 0], de[h8 * 4 + 1]);
                if (rhi < N_NODES)
                    *(__half2*)(g_h1 + (size_t)rhi * HID + col) =
                        __floats2half2_rn(de[h8 * 4 + 2], de[h8 * 4 + 3]);
            }
        }
    }
}

// ---------------- gather1 fused with mm2 (h1 fp16, 4-wide MLP, fused col+nrm) ----------------
__global__ void __launch_bounds__(256) gather1_mm2(const float* __restrict__ b1,
                                                   const float* __restrict__ W2) {
    __shared__ float4 w2t4[NC * 32];
    for (int t = threadIdx.x; t < NC * 32; t += 256) {
        int c = t >> 5, l = t & 31;
        w2t4[t] = make_float4(W2[(4 * l + 0) * NC + c], W2[(4 * l + 1) * NC + c],
                              W2[(4 * l + 2) * NC + c], W2[(4 * l + 3) * NC + c]);
    }
    __syncthreads();

    int warp = threadIdx.x >> 5, lane = threadIdx.x & 31;
    int i = blockIdx.x * 8 + warp;
    if (i >= N_NODES) return;

    float dd = g_dinv[i];
    int start = g_rowptr[i], cnt = g_deg[i];

    float4 acc = make_float4(0.f, 0.f, 0.f, 0.f);
    {
        uint2 u = ((const uint2*)(g_h1 + (size_t)i * HID))[lane];
        fma_h4(acc, u, dd * dd);
    }

    for (int base = 0; base < cnt; base += 32) {
        int j = base + lane;
        int cid = 0; float nv = 0.f;
        if (j < cnt) {
            int2 e2 = g_cole[start + j];
            cid = e2.x;
            nv  = __int_as_float(e2.y);
        }
        int m = cnt - base; if (m > 32) m = 32;
        int k = 0;
        for (; k + 4 <= m; k += 4) {
            int   s0 = __shfl_sync(0xFFFFFFFFu, cid, k);
            int   s1 = __shfl_sync(0xFFFFFFFFu, cid, k + 1);
            int   s2 = __shfl_sync(0xFFFFFFFFu, cid, k + 2);
            int   s3 = __shfl_sync(0xFFFFFFFFu, cid, k + 3);
            float n0 = __shfl_sync(0xFFFFFFFFu, nv, k)     * dd;
            float n1 = __shfl_sync(0xFFFFFFFFu, nv, k + 1) * dd;
            float n2 = __shfl_sync(0xFFFFFFFFu, nv, k + 2) * dd;
            float n3 = __shfl_sync(0xFFFFFFFFu, nv, k + 3) * dd;
            uint2 u0 = ((const uint2*)(g_h1 + (size_t)s0 * HID))[lane];
            uint2 u1 = ((const uint2*)(g_h1 + (size_t)s1 * HID))[lane];
            uint2 u2 = ((const uint2*)(g_h1 + (size_t)s2 * HID))[lane];
            uint2 u3 = ((const uint2*)(g_h1 + (size_t)s3 * HID))[lane];
            fma_h4(acc, u0, n0);
            fma_h4(acc, u1, n1);
            fma_h4(acc, u2, n2);
            fma_h4(acc, u3, n3);
        }
        for (; k < m; k++) {
            int   s   = __shfl_sync(0xFFFFFFFFu, cid, k);
            float nrm = __shfl_sync(0xFFFFFFFFu, nv,  k) * dd;
            uint2 u = ((const uint2*)(g_h1 + (size_t)s * HID))[lane];
            fma_h4(acc, u, nrm);
        }
    }
    float4 b = ((const float4*)b1)[lane];
    acc.x = fmaxf(acc.x + b.x, 0.f);
    acc.y = fmaxf(acc.y + b.y, 0.f);
    acc.z = fmaxf(acc.z + b.z, 0.f);
    acc.w = fmaxf(acc.w + b.w, 0.f);

    float r[NC];
    #pragma unroll
    for (int c = 0; c < NC; c++) {
        float4 w = w2t4[c * 32 + lane];
        float p = acc.x * w.x + acc.y * w.y + acc.z * w.z + acc.w * w.w;
        #pragma unroll
        for (int o = 16; o; o >>= 1) p += __shfl_xor_sync(0xFFFFFFFFu, p, o);
        r[c] = p;
    }
    if (lane == 0) {
        float* o = g_h2 + (size_t)i * NCP;
        *(float4*)(o)     = make_float4(r[0], r[1], r[2], r[3]);
        *(float4*)(o + 4) = make_float4(r[4], r[5], r[6], r[7]);
        *(float2*)(o + 8) = make_float2(r[8], r[9]);
    }
}

// ---------------- gather2 + softmax (4-wide MLP, fused col+nrm) ----------------
__global__ void __launch_bounds__(256) gather2(const float* __restrict__ b2,
                                               float* __restrict__ out) {
    int warp = threadIdx.x >> 5, lane = threadIdx.x & 31;
    int i = blockIdx.x * 8 + warp;
    if (i >= N_NODES) return;

    float dd = g_dinv[i];
    int start = g_rowptr[i], cnt = g_deg[i];

    float acc = 0.f;
    if (lane < NC) acc = g_h2[(size_t)i * NCP + lane] * dd * dd;

    for (int base = 0; base < cnt; base += 32) {
        int j = base + lane;
        int cid = 0; float nv = 0.f;
        if (j < cnt) {
            int2 e2 = g_cole[start + j];
            cid = e2.x;
            nv  = __int_as_float(e2.y);
        }
        int m = cnt - base; if (m > 32) m = 32;
        int k = 0;
        for (; k + 4 <= m; k += 4) {
            int   s0 = __shfl_sync(0xFFFFFFFFu, cid, k);
            int   s1 = __shfl_sync(0xFFFFFFFFu, cid, k + 1);
            int   s2 = __shfl_sync(0xFFFFFFFFu, cid, k + 2);
            int   s3 = __shfl_sync(0xFFFFFFFFu, cid, k + 3);
            float n0 = __shfl_sync(0xFFFFFFFFu, nv, k)     * dd;
            float n1 = __shfl_sync(0xFFFFFFFFu, nv, k + 1) * dd;
            float n2 = __shfl_sync(0xFFFFFFFFu, nv, k + 2) * dd;
            float n3 = __shfl_sync(0xFFFFFFFFu, nv, k + 3) * dd;
            float v0 = 0.f, v1 = 0.f, v2 = 0.f, v3 = 0.f;
            if (lane < NC) {
                v0 = g_h2[(size_t)s0 * NCP + lane];
                v1 = g_h2[(size_t)s1 * NCP + lane];
                v2 = g_h2[(size_t)s2 * NCP + lane];
                v3 = g_h2[(size_t)s3 * NCP + lane];
            }
            acc = fmaf(v0, n0, acc);
            acc = fmaf(v1, n1, acc);
            acc = fmaf(v2, n2, acc);
            acc = fmaf(v3, n3, acc);
        }
        for (; k < m; k++) {
            int   s   = __shfl_sync(0xFFFFFFFFu, cid, k);
            float nrm = __shfl_sync(0xFFFFFFFFu, nv,  k) * dd;
            float v = (lane < NC) ? g_h2[(size_t)s * NCP + lane] : 0.f;
            acc = fmaf(v, nrm, acc);
        }
    }

    float val = (lane < NC) ? acc + b2[lane] : -INFINITY;
    float mx = val;
    #pragma unroll
    for (int o = 16; o; o >>= 1) mx = fmaxf(mx, __shfl_xor_sync(0xFFFFFFFFu, mx, o));
    float e = (lane < NC) ? expf(val - mx) : 0.f;
    float ssum = e;
    #pragma unroll
    for (int o = 16; o; o >>= 1) ssum += __shfl_xor_sync(0xFFFFFFFFu, ssum, o);
    if (lane < NC) out[(size_t)i * NC + lane] = e / ssum;
}

// ---------------- launch ----------------
extern "C" void kernel_launch(void* const* d_in, const int* in_sizes, int n_in,
                              void* d_out, int out_size) {
    const float* x  = (const float*)d_in[0];
    const int*   ei = (const int*)d_in[1];
    const float* W1 = (const float*)d_in[2];
    const float* b1 = (const float*)d_in[3];
    const float* W2 = (const float*)d_in[4];
    const float* b2 = (const float*)d_in[5];
    float* out = (float*)d_out;

    static bool attrDone = false;
    if (!attrDone) {
        cudaFuncSetAttribute(mm1_mma, cudaFuncAttributeMaxDynamicSharedMemorySize, MM1_SMEM);
        attrDone = true;
    }

    w_split<<<(HID * IN_F + 255) / 256, 256>>>(W1);      // 0
    detect_dtype<<<1, 32>>>(ei);                          // 1
    zero_deg<<<(N_NODES + 255) / 256, 256>>>();           // 2
    mm1_mma<<<MM1_TILES, 512, MM1_SMEM>>>(x);             // 3  <- profiled slot
    convert_edges<<<(N_EDGES + 255) / 256, 256>>>(ei);    // 4
    scanA<<<SCAN_B, SCAN_T>>>();
    scanB<<<1, 128>>>();
    scanC<<<SCAN_B, SCAN_T>>>();
    fill_csr<<<(N_EDGES + 255) / 256, 256>>>();

    gather1_mm2<<<N_NODES / 8, 256>>>(b1, W2);
    gather2<<<N_NODES / 8, 256>>>(b2, out);
}

// round 17
// speedup vs baseline: 1.5650x; 1.0029x over previous
#include <cuda_runtime.h>
#include <cuda_bf16.h>
#include <cuda_fp16.h>
#include <math.h>

#define N_NODES 100000
#define N_EDGES 1600000
#define IN_F 128
#define HID 128
#define NC 10
#define NCP 12
#define SCAN_B 98
#define SCAN_T 1024
#define MM1_TILES ((N_NODES + 255) / 256)   // 391
#define A_TILE 65536                         // 256x128 bf16
#define B_TILE 32768                         // 128x128 bf16
#define MM1_SMEM (2 * A_TILE + 2 * B_TILE)   // 192KB

// ---------------- scratch (static device globals; no allocs) ----------------
__device__ int   g_is64;
__device__ int   g_deg   [N_NODES];
__device__ int   g_rowptr[N_NODES];
__device__ int   g_cursor[N_NODES];
__device__ float g_dinv  [N_NODES];
__device__ __align__(16) int2 g_cole[N_EDGES];   // {src, bits(dinv[src])} per edge
__device__ int   g_src   [N_EDGES];
__device__ int   g_dst   [N_EDGES];
__device__ int   g_bsum  [SCAN_B];
__device__ int   g_boff  [SCAN_B];
__device__ unsigned short gWhi[HID * IN_F];   // W1^T split hi, [n][k] bf16
__device__ unsigned short gWlo[HID * IN_F];   // W1^T split lo
__device__ __align__(16) __half g_h1[N_NODES * HID];   // X @ W1, fp16
__device__ __align__(16) float  g_h2[N_NODES * NCP];

// swizzled byte offset in a Rx128 bf16 tile (row r, k col; k multiple of 4)
__device__ __forceinline__ unsigned tile_off(int r, int k) {
    return (unsigned)(r * 256 + ((((k >> 3) ^ (r & 7)) << 4)) + (k & 7) * 2);
}
__device__ __forceinline__ unsigned smem_u32(const void* p) {
    unsigned a;
    asm("{ .reg .u64 t; cvta.to.shared.u64 t, %1; cvt.u32.u64 %0, t; }" : "=r"(a) : "l"(p));
    return a;
}
#define LDSM4(r0, r1, r2, r3, addr) \
    asm volatile("ldmatrix.sync.aligned.m8n8.x4.shared.b16 {%0,%1,%2,%3}, [%4];" \
                 : "=r"(r0), "=r"(r1), "=r"(r2), "=r"(r3) : "r"(addr))
#define MMA16816(d0, d1, d2, d3, a0, a1, a2, a3, b0, b1) \
    asm volatile("mma.sync.aligned.m16n8k16.row.col.f32.bf16.bf16.f32 " \
                 "{%0,%1,%2,%3}, {%4,%5,%6,%7}, {%8,%9}, {%0,%1,%2,%3};" \
                 : "+f"(d0), "+f"(d1), "+f"(d2), "+f"(d3) \
                 : "r"(a0), "r"(a1), "r"(a2), "r"(a3), "r"(b0), "r"(b1))

__device__ __forceinline__ void fma_h4(float4& acc, uint2 u, float nrm) {
    float2 p0 = __half22float2(*(__half2*)&u.x);
    float2 p1 = __half22float2(*(__half2*)&u.y);
    acc.x = fmaf(p0.x, nrm, acc.x);
    acc.y = fmaf(p0.y, nrm, acc.y);
    acc.z = fmaf(p1.x, nrm, acc.z);
    acc.w = fmaf(p1.y, nrm, acc.w);
}

// ---------------- dtype sniff ----------------
__global__ void detect_dtype(const int* __restrict__ raw) {
    if (threadIdx.x == 0 && blockIdx.x == 0) {
        int any = 0;
        #pragma unroll
        for (int k = 0; k < 8; k++) any |= raw[2 * k + 1];
        g_is64 = (any == 0) ? 1 : 0;
    }
}

__global__ void zero_deg() {
    int i = blockIdx.x * blockDim.x + threadIdx.x;
    if (i < N_NODES) g_deg[i] = 0;
}

__global__ void convert_edges(const int* __restrict__ raw) {
    int e = blockIdx.x * blockDim.x + threadIdx.x;
    if (e >= N_EDGES) return;
    int s, d;
    if (g_is64) {
        s = ((const int2*)raw)[e].x;
        d = ((const int2*)raw)[N_EDGES + e].x;
    } else {
        s = raw[e];
        d = raw[N_EDGES + e];
    }
    g_src[e] = s;
    g_dst[e] = d;
    atomicAdd(&g_deg[d], 1);
}

// ---------------- W1 split ----------------
__global__ void w_split(const float* __restrict__ W1) {
    int idx = blockIdx.x * blockDim.x + threadIdx.x;
    if (idx >= HID * IN_F) return;
    int n = idx >> 7, k = idx & 127;
    float w = W1[k * HID + n];
    __nv_bfloat16 hi = __float2bfloat16(w);
    __nv_bfloat16 lo = __float2bfloat16(w - __bfloat162float(hi));
    gWhi[idx] = __bfloat16_as_ushort(hi);
    gWlo[idx] = __bfloat16_as_ushort(lo);
}

// ---------------- scans ----------------
__global__ void __launch_bounds__(SCAN_T) scanA() {
    __shared__ int wsum[32];
    int i = blockIdx.x * SCAN_T + threadIdx.x;
    int lane = threadIdx.x & 31, warp = threadIdx.x >> 5;
    int d = (i < N_NODES) ? g_deg[i] : 0;
    int v = d;
    #pragma unroll
    for (int o = 16; o; o >>= 1) v += __shfl_xor_sync(0xFFFFFFFFu, v, o);
    if (lane == 0) wsum[warp] = v;
    __syncthreads();
    if (warp == 0) {
        int w = wsum[lane];
        #pragma unroll
        for (int o = 16; o; o >>= 1) w += __shfl_xor_sync(0xFFFFFFFFu, w, o);
        if (lane == 0) g_bsum[blockIdx.x] = w;
    }
}
__global__ void __launch_bounds__(128) scanB() {
    __shared__ int wsum[4];
    int t = threadIdx.x;
    int lane = t & 31, warp = t >> 5;
    int s = (t < SCAN_B) ? g_bsum[t] : 0;
    int v = s;
    #pragma unroll
    for (int o = 1; o < 32; o <<= 1) {
        int n = __shfl_up_sync(0xFFFFFFFFu, v, o);
        if (lane >= o) v += n;
    }
    if (lane == 31) wsum[warp] = v;
    __syncthreads();
    int off = 0;
    for (int w = 0; w < warp; w++) off += wsum[w];
    if (t < SCAN_B) g_boff[t] = off + v - s;
}
__global__ void __launch_bounds__(SCAN_T) scanC() {
    __shared__ int wsum[32];
    int i = blockIdx.x * SCAN_T + threadIdx.x;
    int lane = threadIdx.x & 31, warp = threadIdx.x >> 5;
    int d = (i < N_NODES) ? g_deg[i] : 0;
    int v = d;
    #pragma unroll
    for (int o = 1; o < 32; o <<= 1) {
        int n = __shfl_up_sync(0xFFFFFFFFu, v, o);
        if (lane >= o) v += n;
    }
    if (lane == 31) wsum[warp] = v;
    __syncthreads();
    if (warp == 0) {
        int w = wsum[lane];
        #pragma unroll
        for (int o = 1; o < 32; o <<= 1) {
            int n = __shfl_up_sync(0xFFFFFFFFu, w, o);
            if (lane >= o) w += n;
        }
        wsum[lane] = w;
    }
    __syncthreads();
    if (i < N_NODES) {
        int p = g_boff[blockIdx.x] + (warp ? wsum[warp - 1] : 0) + (v - d);
        g_rowptr[i] = p;
        g_cursor[i] = p;
        g_dinv[i]   = rsqrtf((float)d + 1.0f);
    }
}

// ---------------- CSR fill: store {src, dinv[src]} per slot ----------------
__global__ void fill_csr() {
    int e = blockIdx.x * blockDim.x + threadIdx.x;
    if (e < N_EDGES) {
        int s = g_src[e];
        int d = g_dst[e];
        int p = atomicAdd(&g_cursor[d], 1);
        g_cole[p] = make_int2(s, __float_as_int(g_dinv[s]));
    }
}

// ---------------- mm1: 512 threads, CTA tile 256x128; warp tile 32x64; fp16 output ----------------
__global__ void __launch_bounds__(512) mm1_mma(const float* __restrict__ x) {
    extern __shared__ char sm[];
    char* smAhi = sm;
    char* smAlo = sm + A_TILE;
    char* smBhi = sm + 2 * A_TILE;
    char* smBlo = sm + 2 * A_TILE + B_TILE;

    const int tid = threadIdx.x;
    const int wid = tid >> 5, lane = tid & 31;
    const int row0 = blockIdx.x * 256;

    #pragma unroll 4
    for (int it = 0; it < 16; it++) {
        int idx4 = tid + it * 512;
        int r  = idx4 >> 5;
        int k0 = (idx4 & 31) * 4;
        int grow = row0 + r;
        float4 v = make_float4(0.f, 0.f, 0.f, 0.f);
        if (grow < N_NODES) v = ((const float4*)x)[(size_t)grow * 32 + (idx4 & 31)];
        __nv_bfloat16 h0 = __float2bfloat16(v.x), h1b = __float2bfloat16(v.y);
        __nv_bfloat16 h2 = __float2bfloat16(v.z), h3 = __float2bfloat16(v.w);
        __nv_bfloat16 l0 = __float2bfloat16(v.x - __bfloat162float(h0));
        __nv_bfloat16 l1 = __float2bfloat16(v.y - __bfloat162float(h1b));
        __nv_bfloat16 l2 = __float2bfloat16(v.z - __bfloat162float(h2));
        __nv_bfloat16 l3 = __float2bfloat16(v.w - __bfloat162float(h3));
        unsigned hiA = (unsigned)__bfloat16_as_ushort(h0) | ((unsigned)__bfloat16_as_ushort(h1b) << 16);
        unsigned hiB = (unsigned)__bfloat16_as_ushort(h2) | ((unsigned)__bfloat16_as_ushort(h3) << 16);
        unsigned loA = (unsigned)__bfloat16_as_ushort(l0) | ((unsigned)__bfloat16_as_ushort(l1) << 16);
        unsigned loB = (unsigned)__bfloat16_as_ushort(l2) | ((unsigned)__bfloat16_as_ushort(l3) << 16);
        unsigned off = tile_off(r, k0);
        *(uint2*)(smAhi + off) = make_uint2(hiA, hiB);
        *(uint2*)(smAlo + off) = make_uint2(loA, loB);
    }

    #pragma unroll 4
    for (int it = 0; it < 8; it++) {
        int idx4 = tid + it * 512;
        int n  = idx4 >> 5;
        int k0 = (idx4 & 31) * 4;
        uint2 bh = *(const uint2*)(gWhi + n * 128 + k0);
        uint2 bl = *(const uint2*)(gWlo + n * 128 + k0);
        unsigned off = tile_off(n, k0);
        *(uint2*)(smBhi + off) = bh;
        *(uint2*)(smBlo + off) = bl;
    }
    __syncthreads();

    const int wm = (wid & 7) * 32;
    const int wn = (wid >> 3) * 64;
    const int a_lrow = lane & 15;
    const int a_koff = (lane & 16) ? 8 : 0;
    const int b_lrow = (lane & 7) + ((lane & 16) ? 8 : 0);
    const int b_koff = (lane & 8) ? 8 : 0;

    float d[2][4][8];
    #pragma unroll
    for (int a = 0; a < 2; a++)
        #pragma unroll
        for (int b = 0; b < 4; b++)
            #pragma unroll
            for (int c = 0; c < 8; c++) d[a][b][c] = 0.f;

    #pragma unroll
    for (int ks = 0; ks < 8; ks++) {
        int k = ks * 16;
        unsigned a0h0, a0h1, a0h2, a0h3, a1h0, a1h1, a1h2, a1h3;
        unsigned a0l0, a0l1, a0l2, a0l3, a1l0, a1l1, a1l2, a1l3;
        unsigned aoff0 = tile_off(wm + a_lrow, k + a_koff);
        unsigned aoff1 = tile_off(wm + 16 + a_lrow, k + a_koff);
        LDSM4(a0h0, a0h1, a0h2, a0h3, smem_u32(smAhi + aoff0));
        LDSM4(a1h0, a1h1, a1h2, a1h3, smem_u32(smAhi + aoff1));
        LDSM4(a0l0, a0l1, a0l2, a0l3, smem_u32(smAlo + aoff0));
        LDSM4(a1l0, a1l1, a1l2, a1l3, smem_u32(smAlo + aoff1));
        #pragma unroll
        for (int nt = 0; nt < 4; nt++) {
            float* d0 = d[0][nt];
            float* d1 = d[1][nt];
            unsigned boff = tile_off(wn + nt * 16 + b_lrow, k + b_koff);
            unsigned b0, b1, b2, b3;
            LDSM4(b0, b1, b2, b3, smem_u32(smBhi + boff));
            MMA16816(d0[0], d0[1], d0[2], d0[3], a0h0, a0h1, a0h2, a0h3, b0, b1);
            MMA16816(d0[4], d0[5], d0[6], d0[7], a0h0, a0h1, a0h2, a0h3, b2, b3);
            MMA16816(d1[0], d1[1], d1[2], d1[3], a1h0, a1h1, a1h2, a1h3, b0, b1);
            MMA16816(d1[4], d1[5], d1[6], d1[7], a1h0, a1h1, a1h2, a1h3, b2, b3);
            MMA16816(d0[0], d0[1], d0[2], d0[3], a0l0, a0l1, a0l2, a0l3, b0, b1);
            MMA16816(d0[4], d0[5], d0[6], d0[7], a0l0, a0l1, a0l2, a0l3, b2, b3);
            MMA16816(d1[0], d1[1], d1[2], d1[3], a1l0, a1l1, a1l2, a1l3, b0, b1);
            MMA16816(d1[4], d1[5], d1[6], d1[7], a1l0, a1l1, a1l2, a1l3, b2, b3);
            LDSM4(b0, b1, b2, b3, smem_u32(smBlo + boff));
            MMA16816(d0[0], d0[1], d0[2], d0[3], a0h0, a0h1, a0h2, a0h3, b0, b1);
            MMA16816(d0[4], d0[5], d0[6], d0[7], a0h0, a0h1, a0h2, a0h3, b2, b3);
            MMA16816(d1[0], d1[1], d1[2], d1[3], a1h0, a1h1, a1h2, a1h3, b0, b1);
            MMA16816(d1[4], d1[5], d1[6], d1[7], a1h0, a1h1, a1h2, a1h3, b2, b3);
        }
    }

    int g = lane >> 2, tig = lane & 3;
    #pragma unroll
    for (int mh = 0; mh < 2; mh++) {
        int rlo = row0 + wm + mh * 16 + g;
        int rhi = rlo + 8;
        #pragma unroll
        for (int nt = 0; nt < 4; nt++) {
            const float* de = d[mh][nt];
            #pragma unroll
            for (int h8 = 0; h8 < 2; h8++) {
                int col = wn + nt * 16 + h8 * 8 + tig * 2;
                if (rlo < N_NODES)
                    *(__half2*)(g_h1 + (size_t)rlo * HID + col) =
                        __floats2half2_rn(de[h8 * 4 + 0], de[h8 * 4 + 1]);
                if (rhi < N_NODES)
                    *(__half2*)(g_h1 + (size_t)rhi * HID + col) =
                        __floats2half2_rn(de[h8 * 4 + 2], de[h8 * 4 + 3]);
            }
        }
    }
}

// ---------------- gather1 fused with mm2 (h1 fp16, 4-wide MLP, occ 6) ----------------
__global__ void __launch_bounds__(256, 6) gather1_mm2(const float* __restrict__ b1,
                                                      const float* __restrict__ W2) {
    __shared__ float4 w2t4[NC * 32];
    for (int t = threadIdx.x; t < NC * 32; t += 256) {
        int c = t >> 5, l = t & 31;
        w2t4[t] = make_float4(W2[(4 * l + 0) * NC + c], W2[(4 * l + 1) * NC + c],
                              W2[(4 * l + 2) * NC + c], W2[(4 * l + 3) * NC + c]);
    }
    __syncthreads();

    int warp = threadIdx.x >> 5, lane = threadIdx.x & 31;
    int i = blockIdx.x * 8 + warp;
    if (i >= N_NODES) return;

    float dd = g_dinv[i];
    int start = g_rowptr[i], cnt = g_deg[i];

    float4 acc = make_float4(0.f, 0.f, 0.f, 0.f);
    {
        uint2 u = ((const uint2*)(g_h1 + (size_t)i * HID))[lane];
        fma_h4(acc, u, dd * dd);
    }

    for (int base = 0; base < cnt; base += 32) {
        int j = base + lane;
        int cid = 0; float nv = 0.f;
        if (j < cnt) {
            int2 e2 = g_cole[start + j];
            cid = e2.x;
            nv  = __int_as_float(e2.y);
        }
        int m = cnt - base; if (m > 32) m = 32;
        int k = 0;
        for (; k + 4 <= m; k += 4) {
            int   s0 = __shfl_sync(0xFFFFFFFFu, cid, k);
            int   s1 = __shfl_sync(0xFFFFFFFFu, cid, k + 1);
            int   s2 = __shfl_sync(0xFFFFFFFFu, cid, k + 2);
            int   s3 = __shfl_sync(0xFFFFFFFFu, cid, k + 3);
            float n0 = __shfl_sync(0xFFFFFFFFu, nv, k)     * dd;
            float n1 = __shfl_sync(0xFFFFFFFFu, nv, k + 1) * dd;
            float n2 = __shfl_sync(0xFFFFFFFFu, nv, k + 2) * dd;
            float n3 = __shfl_sync(0xFFFFFFFFu, nv, k + 3) * dd;
            uint2 u0 = ((const uint2*)(g_h1 + (size_t)s0 * HID))[lane];
            uint2 u1 = ((const uint2*)(g_h1 + (size_t)s1 * HID))[lane];
            uint2 u2 = ((const uint2*)(g_h1 + (size_t)s2 * HID))[lane];
            uint2 u3 = ((const uint2*)(g_h1 + (size_t)s3 * HID))[lane];
            fma_h4(acc, u0, n0);
            fma_h4(acc, u1, n1);
            fma_h4(acc, u2, n2);
            fma_h4(acc, u3, n3);
        }
        for (; k < m; k++) {
            int   s   = __shfl_sync(0xFFFFFFFFu, cid, k);
            float nrm = __shfl_sync(0xFFFFFFFFu, nv,  k) * dd;
            uint2 u = ((const uint2*)(g_h1 + (size_t)s * HID))[lane];
            fma_h4(acc, u, nrm);
        }
    }
    float4 b = ((const float4*)b1)[lane];
    acc.x = fmaxf(acc.x + b.x, 0.f);
    acc.y = fmaxf(acc.y + b.y, 0.f);
    acc.z = fmaxf(acc.z + b.z, 0.f);
    acc.w = fmaxf(acc.w + b.w, 0.f);

    float r[NC];
    #pragma unroll
    for (int c = 0; c < NC; c++) {
        float4 w = w2t4[c * 32 + lane];
        float p = acc.x * w.x + acc.y * w.y + acc.z * w.z + acc.w * w.w;
        #pragma unroll
        for (int o = 16; o; o >>= 1) p += __shfl_xor_sync(0xFFFFFFFFu, p, o);
        r[c] = p;
    }
    if (lane == 0) {
        float* o = g_h2 + (size_t)i * NCP;
        *(float4*)(o)     = make_float4(r[0], r[1], r[2], r[3]);
        *(float4*)(o + 4) = make_float4(r[4], r[5], r[6], r[7]);
        *(float2*)(o + 8) = make_float2(r[8], r[9]);
    }
}

// ---------------- gather2 + softmax (4-wide MLP, occ 6) ----------------
__global__ void __launch_bounds__(256, 6) gather2(const float* __restrict__ b2,
                                                  float* __restrict__ out) {
    int warp = threadIdx.x >> 5, lane = threadIdx.x & 31;
    int i = blockIdx.x * 8 + warp;
    if (i >= N_NODES) return;

    float dd = g_dinv[i];
    int start = g_rowptr[i], cnt = g_deg[i];

    float acc = 0.f;
    if (lane < NC) acc = g_h2[(size_t)i * NCP + lane] * dd * dd;

    for (int base = 0; base < cnt; base += 32) {
        int j = base + lane;
        int cid = 0; float nv = 0.f;
        if (j < cnt) {
            int2 e2 = g_cole[start + j];
            cid = e2.x;
            nv  = __int_as_float(e2.y);
        }
        int m = cnt - base; if (m > 32) m = 32;
        int k = 0;
        for (; k + 4 <= m; k += 4) {
            int   s0 = __shfl_sync(0xFFFFFFFFu, cid, k);
            int   s1 = __shfl_sync(0xFFFFFFFFu, cid, k + 1);
            int   s2 = __shfl_sync(0xFFFFFFFFu, cid, k + 2);
            int   s3 = __shfl_sync(0xFFFFFFFFu, cid, k + 3);
            float n0 = __shfl_sync(0xFFFFFFFFu, nv, k)     * dd;
            float n1 = __shfl_sync(0xFFFFFFFFu, nv, k + 1) * dd;
            float n2 = __shfl_sync(0xFFFFFFFFu, nv, k + 2) * dd;
            float n3 = __shfl_sync(0xFFFFFFFFu, nv, k + 3) * dd;
            float v0 = 0.f, v1 = 0.f, v2 = 0.f, v3 = 0.f;
            if (lane < NC) {
                v0 = g_h2[(size_t)s0 * NCP + lane];
                v1 = g_h2[(size_t)s1 * NCP + lane];
                v2 = g_h2[(size_t)s2 * NCP + lane];
                v3 = g_h2[(size_t)s3 * NCP + lane];
            }
            acc = fmaf(v0, n0, acc);
            acc = fmaf(v1, n1, acc);
            acc = fmaf(v2, n2, acc);
            acc = fmaf(v3, n3, acc);
        }
        for (; k < m; k++) {
            int   s   = __shfl_sync(0xFFFFFFFFu, cid, k);
            float nrm = __shfl_sync(0xFFFFFFFFu, nv,  k) * dd;
            float v = (lane < NC) ? g_h2[(size_t)s * NCP + lane] : 0.f;
            acc = fmaf(v, nrm, acc);
        }
    }

    float val = (lane < NC) ? acc + b2[lane] : -INFINITY;
    float mx = val;
    #pragma unroll
    for (int o = 16; o; o >>= 1) mx = fmaxf(mx, __shfl_xor_sync(0xFFFFFFFFu, mx, o));
    float e = (lane < NC) ? expf(val - mx) : 0.f;
    float ssum = e;
    #pragma unroll
    for (int o = 16; o; o >>= 1) ssum += __shfl_xor_sync(0xFFFFFFFFu, ssum, o);
    if (lane < NC) out[(size_t)i * NC + lane] = e / ssum;
}

// ---------------- launch ----------------
extern "C" void kernel_launch(void* const* d_in, const int* in_sizes, int n_in,
                              void* d_out, int out_size) {
    const float* x  = (const float*)d_in[0];
    const int*   ei = (const int*)d_in[1];
    const float* W1 = (const float*)d_in[2];
    const float* b1 = (const float*)d_in[3];
    const float* W2 = (const float*)d_in[4];
    const float* b2 = (const float*)d_in[5];
    float* out = (float*)d_out;

    static bool attrDone = false;
    if (!attrDone) {
        cudaFuncSetAttribute(mm1_mma, cudaFuncAttributeMaxDynamicSharedMemorySize, MM1_SMEM);
        attrDone = true;
    }

    w_split<<<(HID * IN_F + 255) / 256, 256>>>(W1);      // 0
    detect_dtype<<<1, 32>>>(ei);                          // 1
    zero_deg<<<(N_NODES + 255) / 256, 256>>>();           // 2
    mm1_mma<<<MM1_TILES, 512, MM1_SMEM>>>(x);             // 3  <- profiled slot
    convert_edges<<<(N_EDGES + 255) / 256, 256>>>(ei);    // 4
    scanA<<<SCAN_B, SCAN_T>>>();
    scanB<<<1, 128>>>();
    scanC<<<SCAN_B, SCAN_T>>>();
    fill_csr<<<(N_EDGES + 255) / 256, 256>>>();

    gather1_mm2<<<N_NODES / 8, 256>>>(b1, W2);
    gather2<<<N_NODES / 8, 256>>>(b2, out);
}